// round 15
// baseline (speedup 1.0000x reference)
#include <cuda_runtime.h>
#include <cuda_bf16.h>
#include <math.h>
#include <stdint.h>

// Problem constants
#define BATCH 4
#define SEQ   2048
#define DIM   256
#define HEADS 4
#define DEPTH 64
#define HID   1024
#define MROWS (BATCH*SEQ)      // 8192
#define EPS   1e-3f
#define QSC   0.18033688011112042f   // 0.125 * log2(e)

// ===================== PTX helpers ==========================================
__device__ __forceinline__ uint32_t smem_u32(const void* p) {
    uint32_t a;
    asm("{ .reg .u64 t; cvta.to.shared.u64 t, %1; cvt.u32.u64 %0, t; }"
        : "=r"(a) : "l"(p));
    return a;
}
__device__ __forceinline__ void ldsm4(uint32_t addr, uint32_t* r) {
    asm volatile("ldmatrix.sync.aligned.m8n8.x4.shared.b16 {%0,%1,%2,%3}, [%4];"
                 : "=r"(r[0]), "=r"(r[1]), "=r"(r[2]), "=r"(r[3]) : "r"(addr));
}
__device__ __forceinline__ void ldsm2(uint32_t addr, uint32_t* r) {
    asm volatile("ldmatrix.sync.aligned.m8n8.x2.shared.b16 {%0,%1}, [%2];"
                 : "=r"(r[0]), "=r"(r[1]) : "r"(addr));
}
__device__ __forceinline__ void mma16816(float* c, const uint32_t* a, const uint32_t* b) {
    asm volatile(
        "mma.sync.aligned.m16n8k16.row.col.f32.bf16.bf16.f32 "
        "{%0,%1,%2,%3}, {%4,%5,%6,%7}, {%8,%9}, {%0,%1,%2,%3};"
        : "+f"(c[0]), "+f"(c[1]), "+f"(c[2]), "+f"(c[3])
        : "r"(a[0]), "r"(a[1]), "r"(a[2]), "r"(a[3]), "r"(b[0]), "r"(b[1]));
}
__device__ __forceinline__ void mma1688(float* c, const uint32_t* a, const uint32_t* b) {
    asm volatile(
        "mma.sync.aligned.m16n8k8.row.col.f32.tf32.tf32.f32 "
        "{%0,%1,%2,%3}, {%4,%5,%6,%7}, {%8,%9}, {%0,%1,%2,%3};"
        : "+f"(c[0]), "+f"(c[1]), "+f"(c[2]), "+f"(c[3])
        : "r"(a[0]), "r"(a[1]), "r"(a[2]), "r"(a[3]), "r"(b[0]), "r"(b[1]));
}
__device__ __forceinline__ uint32_t f2tf(float x) {
    uint32_t r; asm("cvt.rna.tf32.f32 %0, %1;" : "=r"(r) : "f"(x)); return r;
}
__device__ __forceinline__ float ex2f(float x) {
    float r; asm("ex2.approx.f32 %0, %1;" : "=f"(r) : "f"(x)); return r;
}

// ===================== scratch (device globals) =============================
#define QR ((size_t)16 * SEQ * DEPTH)      // one attn region (frag-major)
__device__ float g_bqkv[3 * DIM];
__device__ float g_b1f[HID];
__device__ __align__(16) __nv_bfloat16 g_qkvT_hi[3 * DIM * DIM], g_qkvT_lo[3 * DIM * DIM];
__device__ __align__(16) __nv_bfloat16 g_woT_hi[DIM * DIM],      g_woT_lo[DIM * DIM];
__device__ __align__(16) __nv_bfloat16 g_w1T_hi[HID * DIM],      g_w1T_lo[HID * DIM];
__device__ __align__(16) __nv_bfloat16 g_w2T_hi[DIM * HID],      g_w2T_lo[DIM * HID];
__device__ __align__(16) float g_attf[3 * 16 * SEQ * DEPTH];   // q,k,v frag-major
__device__ float g_ctx[MROWS * DIM];
__device__ float g_x1[MROWS * DIM];
__device__ float g_m1[MROWS * HID];

__device__ __forceinline__ void split_bf16(float x, __nv_bfloat16& h, __nv_bfloat16& l) {
    h = __float2bfloat16_rn(x);
    l = __float2bfloat16_rn(x - __bfloat162float(h));
}

// ===================== prep: elementwise split/transpose ====================
#define N_QKV (3 * DIM * DIM)          // 196608
#define N_W1  (DIM * HID)              // 262144
#define N_WO  (DIM * DIM)              // 65536
#define N_W2  (HID * DIM)              // 262144
#define N_TOT (N_QKV + N_W1 + N_WO + N_W2)

__global__ void prep_split(
    const float* __restrict__ g1, const float* __restrict__ v1,
    const float* __restrict__ g2, const float* __restrict__ v2,
    const float* __restrict__ wq, const float* __restrict__ wk,
    const float* __restrict__ wv, const float* __restrict__ w1,
    const float* __restrict__ wo, const float* __restrict__ w2)
{
    int i = blockIdx.x * 256 + threadIdx.x;
    if (i < N_QKV) {
        int d = i / (3 * DIM), col = i % (3 * DIM);
        const float* w = (col < DIM) ? wq : (col < 2 * DIM) ? wk : wv;
        int c = col & (DIM - 1);
        float a = g1[d] * rsqrtf(v1[d] + EPS);
        float val = a * w[d * DIM + c];
        __nv_bfloat16 h, l; split_bf16(val, h, l);
        g_qkvT_hi[col * DIM + d] = h; g_qkvT_lo[col * DIM + d] = l;
    } else if (i < N_QKV + N_W1) {
        int j = i - N_QKV; int d = j / HID, c = j % HID;
        float a = g2[d] * rsqrtf(v2[d] + EPS);
        float val = a * w1[j];
        __nv_bfloat16 h, l; split_bf16(val, h, l);
        g_w1T_hi[c * DIM + d] = h; g_w1T_lo[c * DIM + d] = l;
    } else if (i < N_QKV + N_W1 + N_WO) {
        int j = i - N_QKV - N_W1; int d = j / DIM, c = j % DIM;
        __nv_bfloat16 h, l; split_bf16(wo[j], h, l);
        g_woT_hi[c * DIM + d] = h; g_woT_lo[c * DIM + d] = l;
    } else if (i < N_TOT) {
        int j = i - N_QKV - N_W1 - N_WO; int k = j / DIM, n = j % DIM;
        __nv_bfloat16 h, l; split_bf16(w2[j], h, l);
        g_w2T_hi[n * HID + k] = h; g_w2T_lo[n * HID + k] = l;
    }
}

__global__ void prep_bias(
    const float* __restrict__ g1, const float* __restrict__ b1,
    const float* __restrict__ m1, const float* __restrict__ v1,
    const float* __restrict__ g2, const float* __restrict__ b2,
    const float* __restrict__ m2, const float* __restrict__ v2,
    const float* __restrict__ wq, const float* __restrict__ wk,
    const float* __restrict__ wv,
    const float* __restrict__ bq, const float* __restrict__ bk,
    const float* __restrict__ bv, const float* __restrict__ w1)
{
    int blk = blockIdx.x, t = threadIdx.x;
    if (blk < 3) {
        const float* w  = blk == 0 ? wq : blk == 1 ? wk : wv;
        const float* bb = blk == 0 ? bq : blk == 1 ? bk : bv;
        float acc = bb[t];
        for (int d = 0; d < DIM; d++) {
            float a = g1[d] * rsqrtf(v1[d] + EPS);
            float c = b1[d] - m1[d] * a;
            acc += c * w[d * DIM + t];
        }
        g_bqkv[blk * DIM + t] = acc;
    } else {
        int cb = (blk - 3) * 256;
        float acc = 0.f;
        for (int d = 0; d < DIM; d++) {
            float a = g2[d] * rsqrtf(v2[d] + EPS);
            float c = b2[d] - m2[d] * a;
            acc += c * w1[d * HID + cb + t];
        }
        g_b1f[cb + t] = acc;
    }
}

// ===================== mma.sync split-bf16 GEMM =============================
// mode 0: C = A@B + bias (+resid). mode 1: + GELU. mode 2: frag-major q/k/v
// (tf32-rounded, q pre-scaled by 0.125*log2e) into g_attf.
#define ASTRIDE 40
#define TILE_B  (128 * ASTRIDE * 2)
#define BUF_B   (4 * TILE_B)
#define GSMEM_B (2 * BUF_B)

__global__ void __launch_bounds__(256)
gemm_mma(const float* __restrict__ A,
         const __nv_bfloat16* __restrict__ Bth, const __nv_bfloat16* __restrict__ Btl,
         const float* __restrict__ bias, const float* __restrict__ resid,
         float* __restrict__ C, float* __restrict__ attf,
         int M, int N, int K, int mode)
{
    extern __shared__ __align__(16) char smem[];
    const int tid  = threadIdx.x;
    const int wid  = tid >> 5;
    const int lane = tid & 31;
    const int m0 = blockIdx.y * 128;
    const int n0 = blockIdx.x * 128;
    const int warpM = (wid & 1) * 64;
    const int warpN = (wid >> 1) * 32;

    const int lrow = tid >> 1;
    const int lko  = (tid & 1) * 16;

    const int aRowOff = (lane & 7) + ((lane >> 3) & 1) * 8;
    const int aKpart  = ((lane >> 4) & 1) * 8;
    const int bl2     = lane & 15;
    const int bRowOff = bl2 & 7;
    const int bKpart  = (bl2 >> 3) * 8;

    const uint32_t sbase = smem_u32(smem);

    float acc[4][4][4];
#pragma unroll
    for (int i = 0; i < 4; i++)
#pragma unroll
        for (int j = 0; j < 4; j++)
#pragma unroll
            for (int e = 0; e < 4; e++) acc[i][j][e] = 0.f;

    const int nch = K >> 5;
    float4 aR[4];
    uint4  bhR[2], blR[2];

    {
        const float* ap = A + (size_t)(m0 + lrow) * K + lko;
#pragma unroll
        for (int i = 0; i < 4; i++) aR[i] = ((const float4*)ap)[i];
        const __nv_bfloat16* bp = Bth + (size_t)(n0 + lrow) * K + lko;
        const __nv_bfloat16* lp = Btl + (size_t)(n0 + lrow) * K + lko;
        bhR[0] = ((const uint4*)bp)[0]; bhR[1] = ((const uint4*)bp)[1];
        blR[0] = ((const uint4*)lp)[0]; blR[1] = ((const uint4*)lp)[1];
    }

    for (int c = 0; c < nch; c++) {
        const int buf = c & 1;
        char* base = smem + buf * BUF_B;
        __syncthreads();
        {
            const int rb = lrow * (ASTRIDE * 2) + lko * 2;
#pragma unroll
            for (int i = 0; i < 2; i++) {
                float4 f0 = aR[i * 2], f1 = aR[i * 2 + 1];
                __nv_bfloat162 h01 = __floats2bfloat162_rn(f0.x, f0.y);
                __nv_bfloat162 h23 = __floats2bfloat162_rn(f0.z, f0.w);
                __nv_bfloat162 h45 = __floats2bfloat162_rn(f1.x, f1.y);
                __nv_bfloat162 h67 = __floats2bfloat162_rn(f1.z, f1.w);
                __nv_bfloat162 l01 = __floats2bfloat162_rn(f0.x - __bfloat162float(h01.x),
                                                           f0.y - __bfloat162float(h01.y));
                __nv_bfloat162 l23 = __floats2bfloat162_rn(f0.z - __bfloat162float(h23.x),
                                                           f0.w - __bfloat162float(h23.y));
                __nv_bfloat162 l45 = __floats2bfloat162_rn(f1.x - __bfloat162float(h45.x),
                                                           f1.y - __bfloat162float(h45.y));
                __nv_bfloat162 l67 = __floats2bfloat162_rn(f1.z - __bfloat162float(h67.x),
                                                           f1.w - __bfloat162float(h67.y));
                uint4 hv = { *(uint32_t*)&h01, *(uint32_t*)&h23,
                             *(uint32_t*)&h45, *(uint32_t*)&h67 };
                uint4 lv = { *(uint32_t*)&l01, *(uint32_t*)&l23,
                             *(uint32_t*)&l45, *(uint32_t*)&l67 };
                *(uint4*)(base + rb + i * 16)          = hv;
                *(uint4*)(base + TILE_B + rb + i * 16) = lv;
            }
            *(uint4*)(base + 2 * TILE_B + rb)      = bhR[0];
            *(uint4*)(base + 2 * TILE_B + rb + 16) = bhR[1];
            *(uint4*)(base + 3 * TILE_B + rb)      = blR[0];
            *(uint4*)(base + 3 * TILE_B + rb + 16) = blR[1];
        }
        __syncthreads();

        if (c + 1 < nch) {
            const int k0 = (c + 1) << 5;
            const float* ap = A + (size_t)(m0 + lrow) * K + k0 + lko;
#pragma unroll
            for (int i = 0; i < 4; i++) aR[i] = ((const float4*)ap)[i];
            const __nv_bfloat16* bp = Bth + (size_t)(n0 + lrow) * K + k0 + lko;
            const __nv_bfloat16* lp = Btl + (size_t)(n0 + lrow) * K + k0 + lko;
            bhR[0] = ((const uint4*)bp)[0]; bhR[1] = ((const uint4*)bp)[1];
            blR[0] = ((const uint4*)lp)[0]; blR[1] = ((const uint4*)lp)[1];
        }

        const uint32_t Ah = sbase + buf * BUF_B;
        const uint32_t Al = Ah + TILE_B;
        const uint32_t Bh = Ah + 2 * TILE_B;
        const uint32_t Bl = Ah + 3 * TILE_B;
#pragma unroll
        for (int ks = 0; ks < 2; ks++) {
            uint32_t ah[4][4], al[4][4], bh[4][2], blf[4][2];
#pragma unroll
            for (int mi = 0; mi < 4; mi++) {
                uint32_t off = ((warpM + mi * 16 + aRowOff) * ASTRIDE
                                + ks * 16 + aKpart) * 2;
                ldsm4(Ah + off, ah[mi]);
                ldsm4(Al + off, al[mi]);
            }
#pragma unroll
            for (int nj = 0; nj < 4; nj++) {
                uint32_t off = ((warpN + nj * 8 + bRowOff) * ASTRIDE
                                + ks * 16 + bKpart) * 2;
                ldsm2(Bh + off, bh[nj]);
                ldsm2(Bl + off, blf[nj]);
            }
#pragma unroll
            for (int mi = 0; mi < 4; mi++)
#pragma unroll
                for (int nj = 0; nj < 4; nj++) {
                    mma16816(acc[mi][nj], ah[mi], bh[nj]);
                    mma16816(acc[mi][nj], ah[mi], blf[nj]);
                    mma16816(acc[mi][nj], al[mi], bh[nj]);
                }
        }
    }

    // ---- epilogue ----
    const int g   = lane >> 2;
    const int tig = lane & 3;
#pragma unroll
    for (int mi = 0; mi < 4; mi++) {
#pragma unroll
        for (int half = 0; half < 2; half++) {
            int row = m0 + warpM + mi * 16 + g + half * 8;
#pragma unroll
            for (int nj = 0; nj < 4; nj++) {
                int col = n0 + warpN + nj * 8 + tig * 2;
                float vx = acc[mi][nj][half * 2 + 0];
                float vy = acc[mi][nj][half * 2 + 1];
                if (bias)  { vx += bias[col]; vy += bias[col + 1]; }
                if (mode == 2) {
                    // frag-major q/k/v output
                    int sect = col >> 8;
                    int hh   = (col >> 6) & 3;
                    int d    = col & 63;
                    int b    = row >> 11, sq = row & (SEQ - 1);
                    int bhx  = b * 4 + hh;
                    if (sect == 0) { vx *= QSC; vy *= QSC; }
                    vx = __uint_as_float(f2tf(vx));
                    vy = __uint_as_float(f2tf(vy));
                    size_t fx, fy;
                    if (sect == 0) {
                        int qt = sq >> 7, r = sq & 127;
                        int mtile = r >> 4, r8 = r & 7, hf = (r >> 3) & 1;
                        int kc = d >> 3, ch = (d >> 2) & 1;
                        size_t bse = ((size_t)bhx * 16 + qt) * 8192
                                   + (mtile * 8 + kc) * 128
                                   + (r8 * 4 + (d & 3)) * 4 + hf + 2 * ch;
                        fx = bse; fy = bse + 4;
                    } else if (sect == 1) {
                        int kt = sq >> 6, key = sq & 63;
                        int nt = key >> 3, kcp = d >> 4;
                        int krr = ((d >> 3) & 1) * 2 + ((d >> 2) & 1);
                        size_t bse = ((size_t)bhx * 32 + kt) * 4096
                                   + (nt * 4 + kcp) * 128
                                   + ((key & 7) * 4 + (d & 3)) * 4 + krr;
                        fx = bse; fy = bse + 4;
                    } else {
                        int kt = sq >> 6, key = sq & 63;
                        int nt = d >> 3, kcp = key >> 4;
                        int rr = ((key >> 3) & 1) * 2 + ((key >> 2) & 1);
                        size_t bse = ((size_t)bhx * 32 + kt) * 4096
                                   + (nt * 4 + kcp) * 128
                                   + ((d & 7) * 4 + (key & 3)) * 4 + rr;
                        fx = bse; fy = bse + 16;
                    }
                    float* reg = attf + (size_t)sect * QR;
                    reg[fx] = vx; reg[fy] = vy;
                } else {
                    if (resid) {
                        const float* rp = resid + (size_t)row * N + col;
                        vx += rp[0]; vy += rp[1];
                    }
                    if (mode == 1) {
                        vx = 0.5f * vx * (1.0f + erff(vx * 0.70710678118654752f));
                        vy = 0.5f * vy * (1.0f + erff(vy * 0.70710678118654752f));
                    }
                    *(float2*)(C + (size_t)row * N + col) = make_float2(vx, vy);
                }
            }
        }
    }
}

// ===================== flash attention, tf32 mma ============================
// CTA: 128 queries of one (b,h), 4 warps x 32 rows. Key tiles of 64.
// Q/K/V arrive in gmem frag-major; tile loads are straight uint4 copies.
#define ATP 132                          // padded tile stride (floats)
#define ATT_SMEM (128 * ATP * 4)         // 67584 bytes

__global__ void __launch_bounds__(128)
attn_tf32(const float* __restrict__ attf, float* __restrict__ ctx)
{
    extern __shared__ __align__(16) float sm[];
    float* Qs = sm;                  // 64 tiles
    float* Ks = sm + 64 * ATP;       // 32 tiles
    float* Vs = sm + 96 * ATP;       // 32 tiles

    const int tid  = threadIdx.x;
    const int wid  = tid >> 5;
    const int lane = tid & 31;
    const int bh   = blockIdx.y;
    const int q0   = blockIdx.x * 128;

    // ---- Q tile copy (once) ----
    {
        const uint4* qsrc = (const uint4*)(attf
            + ((size_t)bh * 16 + blockIdx.x) * 8192);
#pragma unroll
        for (int u = 0; u < 16; u++) {
            int g4 = tid + u * 128;
            *(uint4*)(Qs + (g4 >> 5) * ATP + (g4 & 31) * 4) = qsrc[g4];
        }
    }

    float o[2][8][4];
#pragma unroll
    for (int mt = 0; mt < 2; mt++)
#pragma unroll
        for (int nt = 0; nt < 8; nt++)
#pragma unroll
            for (int e = 0; e < 4; e++) o[mt][nt][e] = 0.f;
    float mrow[4] = { -1e30f, -1e30f, -1e30f, -1e30f };
    float lsum[4] = { 0.f, 0.f, 0.f, 0.f };

    const int srcA = (lane & 28) | ((lane & 3) >> 1);
    const int srcB = srcA + 2;
    const bool oddl = lane & 1;

    const uint4* kbase = (const uint4*)(attf + QR)     + (size_t)bh * 32 * 1024;
    const uint4* vbase = (const uint4*)(attf + 2 * QR) + (size_t)bh * 32 * 1024;

    for (int kt = 0; kt < SEQ / 64; kt++) {
        __syncthreads();
        {
            const uint4* ks = kbase + (size_t)kt * 1024;
            const uint4* vs = vbase + (size_t)kt * 1024;
#pragma unroll
            for (int u = 0; u < 8; u++) {
                int g4 = tid + u * 128;
                int off = (g4 >> 5) * ATP + (g4 & 31) * 4;
                *(uint4*)(Ks + off) = ks[g4];
                *(uint4*)(Vs + off) = vs[g4];
            }
        }
        __syncthreads();

        // ---- scores S[32 x 64] per warp ----
        float s[2][8][4];
#pragma unroll
        for (int mt = 0; mt < 2; mt++)
#pragma unroll
            for (int nt = 0; nt < 8; nt++)
#pragma unroll
                for (int e = 0; e < 4; e++) s[mt][nt][e] = 0.f;

#pragma unroll
        for (int kcp = 0; kcp < 4; kcp++) {
            uint4 aE0 = *(const uint4*)(Qs + ((wid * 2 + 0) * 8 + 2 * kcp) * ATP + lane * 4);
            uint4 aO0 = *(const uint4*)(Qs + ((wid * 2 + 0) * 8 + 2 * kcp + 1) * ATP + lane * 4);
            uint4 aE1 = *(const uint4*)(Qs + ((wid * 2 + 1) * 8 + 2 * kcp) * ATP + lane * 4);
            uint4 aO1 = *(const uint4*)(Qs + ((wid * 2 + 1) * 8 + 2 * kcp + 1) * ATP + lane * 4);
#pragma unroll
            for (int nt = 0; nt < 8; nt++) {
                uint4 kb = *(const uint4*)(Ks + (nt * 4 + kcp) * ATP + lane * 4);
                uint32_t bE[2] = { kb.x, kb.y }, bO[2] = { kb.z, kb.w };
                mma1688(s[0][nt], (const uint32_t*)&aE0, bE);
                mma1688(s[0][nt], (const uint32_t*)&aO0, bO);
                mma1688(s[1][nt], (const uint32_t*)&aE1, bE);
                mma1688(s[1][nt], (const uint32_t*)&aO1, bO);
            }
        }

        // ---- online softmax (log2 domain) ----
        float mx[4] = { -1e30f, -1e30f, -1e30f, -1e30f };
#pragma unroll
        for (int mt = 0; mt < 2; mt++)
#pragma unroll
            for (int nt = 0; nt < 8; nt++) {
                mx[2 * mt + 0] = fmaxf(mx[2 * mt + 0], fmaxf(s[mt][nt][0], s[mt][nt][1]));
                mx[2 * mt + 1] = fmaxf(mx[2 * mt + 1], fmaxf(s[mt][nt][2], s[mt][nt][3]));
            }
        float sc[4], ls[4] = { 0.f, 0.f, 0.f, 0.f };
#pragma unroll
        for (int i = 0; i < 4; i++) {
            mx[i] = fmaxf(mx[i], __shfl_xor_sync(0xffffffff, mx[i], 1));
            mx[i] = fmaxf(mx[i], __shfl_xor_sync(0xffffffff, mx[i], 2));
            float mn = fmaxf(mrow[i], mx[i]);
            sc[i] = ex2f(mrow[i] - mn);
            mrow[i] = mn;
        }
#pragma unroll
        for (int mt = 0; mt < 2; mt++)
#pragma unroll
            for (int nt = 0; nt < 8; nt++) {
                s[mt][nt][0] = ex2f(s[mt][nt][0] - mrow[2 * mt]);
                s[mt][nt][1] = ex2f(s[mt][nt][1] - mrow[2 * mt]);
                s[mt][nt][2] = ex2f(s[mt][nt][2] - mrow[2 * mt + 1]);
                s[mt][nt][3] = ex2f(s[mt][nt][3] - mrow[2 * mt + 1]);
                ls[2 * mt]     += s[mt][nt][0] + s[mt][nt][1];
                ls[2 * mt + 1] += s[mt][nt][2] + s[mt][nt][3];
            }
#pragma unroll
        for (int i = 0; i < 4; i++) {
            ls[i] += __shfl_xor_sync(0xffffffff, ls[i], 1);
            ls[i] += __shfl_xor_sync(0xffffffff, ls[i], 2);
            lsum[i] = lsum[i] * sc[i] + ls[i];
        }
#pragma unroll
        for (int mt = 0; mt < 2; mt++)
#pragma unroll
            for (int nt = 0; nt < 8; nt++) {
                o[mt][nt][0] *= sc[2 * mt];     o[mt][nt][1] *= sc[2 * mt];
                o[mt][nt][2] *= sc[2 * mt + 1]; o[mt][nt][3] *= sc[2 * mt + 1];
            }

        // ---- PV: o += P @ V ----
#pragma unroll
        for (int kcp = 0; kcp < 4; kcp++) {
            uint32_t pa[2][2][4];
#pragma unroll
            for (int kk = 0; kk < 2; kk++) {
                int kc = 2 * kcp + kk;
#pragma unroll
                for (int mt = 0; mt < 2; mt++) {
                    float v00 = __shfl_sync(0xffffffff, s[mt][kc][0], srcA);
                    float v01 = __shfl_sync(0xffffffff, s[mt][kc][1], srcA);
                    float v10 = __shfl_sync(0xffffffff, s[mt][kc][2], srcA);
                    float v11 = __shfl_sync(0xffffffff, s[mt][kc][3], srcA);
                    float v20 = __shfl_sync(0xffffffff, s[mt][kc][0], srcB);
                    float v21 = __shfl_sync(0xffffffff, s[mt][kc][1], srcB);
                    float v30 = __shfl_sync(0xffffffff, s[mt][kc][2], srcB);
                    float v31 = __shfl_sync(0xffffffff, s[mt][kc][3], srcB);
                    pa[kk][mt][0] = f2tf(oddl ? v01 : v00);
                    pa[kk][mt][1] = f2tf(oddl ? v11 : v10);
                    pa[kk][mt][2] = f2tf(oddl ? v21 : v20);
                    pa[kk][mt][3] = f2tf(oddl ? v31 : v30);
                }
            }
#pragma unroll
            for (int nt = 0; nt < 8; nt++) {
                uint4 vb = *(const uint4*)(Vs + (nt * 4 + kcp) * ATP + lane * 4);
                uint32_t bE[2] = { vb.x, vb.y }, bO[2] = { vb.z, vb.w };
                mma1688(o[0][nt], pa[0][0], bE);
                mma1688(o[0][nt], pa[1][0], bO);
                mma1688(o[1][nt], pa[0][1], bE);
                mma1688(o[1][nt], pa[1][1], bO);
            }
        }
    }

    // ---- write ctx ----
    float inv[4];
#pragma unroll
    for (int i = 0; i < 4; i++) inv[i] = 1.f / lsum[i];
    const int b  = bh >> 2;
    const int hh = bh & 3;
    const int g  = lane >> 2;
    const int tg = (lane & 3) * 2;
#pragma unroll
    for (int mt = 0; mt < 2; mt++) {
        int ra = q0 + wid * 32 + mt * 16 + g;
#pragma unroll
        for (int nt = 0; nt < 8; nt++) {
            int col = hh * DEPTH + tg + nt * 8;
            *(float2*)(ctx + (size_t)(b * SEQ + ra) * DIM + col) =
                make_float2(o[mt][nt][0] * inv[2 * mt], o[mt][nt][1] * inv[2 * mt]);
            *(float2*)(ctx + (size_t)(b * SEQ + ra + 8) * DIM + col) =
                make_float2(o[mt][nt][2] * inv[2 * mt + 1], o[mt][nt][3] * inv[2 * mt + 1]);
        }
    }
}

// ===================== launch ===============================================
extern "C" void kernel_launch(void* const* d_in, const int* in_sizes, int n_in,
                              void* d_out, int out_size)
{
    const float* x    = (const float*)d_in[0];
    const float* b1g  = (const float*)d_in[1];
    const float* b1b  = (const float*)d_in[2];
    const float* b1m  = (const float*)d_in[3];
    const float* b1v  = (const float*)d_in[4];
    const float* wq   = (const float*)d_in[5];
    const float* bq   = (const float*)d_in[6];
    const float* wk   = (const float*)d_in[7];
    const float* bk   = (const float*)d_in[8];
    const float* wv   = (const float*)d_in[9];
    const float* bv   = (const float*)d_in[10];
    const float* wo   = (const float*)d_in[11];
    const float* bo   = (const float*)d_in[12];
    const float* b2g  = (const float*)d_in[13];
    const float* b2b  = (const float*)d_in[14];
    const float* b2m  = (const float*)d_in[15];
    const float* b2v  = (const float*)d_in[16];
    const float* w1   = (const float*)d_in[17];
    const float* w2   = (const float*)d_in[18];
    float* out = (float*)d_out;

    float *p_bqkv, *p_b1f, *p_ctx, *p_x1, *p_m1, *p_attf;
    __nv_bfloat16 *p_qkvTh, *p_qkvTl, *p_woTh, *p_woTl, *p_w1Th, *p_w1Tl, *p_w2Th, *p_w2Tl;
    cudaGetSymbolAddress((void**)&p_bqkv,  g_bqkv);
    cudaGetSymbolAddress((void**)&p_b1f,   g_b1f);
    cudaGetSymbolAddress((void**)&p_ctx,   g_ctx);
    cudaGetSymbolAddress((void**)&p_x1,    g_x1);
    cudaGetSymbolAddress((void**)&p_m1,    g_m1);
    cudaGetSymbolAddress((void**)&p_attf,  g_attf);
    cudaGetSymbolAddress((void**)&p_qkvTh, g_qkvT_hi);
    cudaGetSymbolAddress((void**)&p_qkvTl, g_qkvT_lo);
    cudaGetSymbolAddress((void**)&p_woTh,  g_woT_hi);
    cudaGetSymbolAddress((void**)&p_woTl,  g_woT_lo);
    cudaGetSymbolAddress((void**)&p_w1Th,  g_w1T_hi);
    cudaGetSymbolAddress((void**)&p_w1Tl,  g_w1T_lo);
    cudaGetSymbolAddress((void**)&p_w2Th,  g_w2T_hi);
    cudaGetSymbolAddress((void**)&p_w2Tl,  g_w2T_lo);

    cudaFuncSetAttribute(gemm_mma, cudaFuncAttributeMaxDynamicSharedMemorySize, GSMEM_B);
    cudaFuncSetAttribute(attn_tf32, cudaFuncAttributeMaxDynamicSharedMemorySize, ATT_SMEM);

    // 1. prep: weight split/transpose (elementwise) + bias folds
    prep_split<<<(N_TOT + 255) / 256, 256>>>(b1g, b1v, b2g, b2v,
                                             wq, wk, wv, w1, wo, w2);
    prep_bias<<<7, 256>>>(b1g, b1b, b1m, b1v, b2g, b2b, b2m, b2v,
                          wq, wk, wv, bq, bk, bv, w1);

    // 2. QKV projection, frag-major tf32 output into g_attf
    gemm_mma<<<dim3(6, 64), 256, GSMEM_B>>>(
        x, p_qkvTh, p_qkvTl, p_bqkv, nullptr, p_ctx, p_attf,
        MROWS, 3 * DIM, DIM, 2);

    // 3. flash attention (tf32 tensor cores) -> g_ctx
    attn_tf32<<<dim3(SEQ / 128, BATCH * HEADS), 128, ATT_SMEM>>>(p_attf, p_ctx);

    // 4. out projection + residual: g_x1 = ctx @ wo + bo + x
    gemm_mma<<<dim3(2, 64), 256, GSMEM_B>>>(
        p_ctx, p_woTh, p_woTl, bo, x, p_x1, p_attf, MROWS, DIM, DIM, 0);

    // 5. FFN1 (BN2 folded) + GELU
    gemm_mma<<<dim3(8, 64), 256, GSMEM_B>>>(
        p_x1, p_w1Th, p_w1Tl, p_b1f, nullptr, p_m1, p_attf, MROWS, HID, DIM, 1);

    // 6. FFN2 + residual: out = m1 @ w2 + x1
    gemm_mma<<<dim3(2, 64), 256, GSMEM_B>>>(
        p_m1, p_w2Th, p_w2Tl, nullptr, p_x1, out, p_attf, MROWS, DIM, HID, 0);
}

// round 16
// speedup vs baseline: 1.0045x; 1.0045x over previous
#include <cuda_runtime.h>
#include <cuda_bf16.h>
#include <math.h>
#include <stdint.h>

// Problem constants
#define BATCH 4
#define SEQ   2048
#define DIM   256
#define HEADS 4
#define DEPTH 64
#define HID   1024
#define MROWS (BATCH*SEQ)      // 8192
#define EPS   1e-3f
#define QSC   0.18033688011112042f   // 0.125 * log2(e)

// ===================== PTX helpers ==========================================
__device__ __forceinline__ uint32_t smem_u32(const void* p) {
    uint32_t a;
    asm("{ .reg .u64 t; cvta.to.shared.u64 t, %1; cvt.u32.u64 %0, t; }"
        : "=r"(a) : "l"(p));
    return a;
}
__device__ __forceinline__ void ldsm4(uint32_t addr, uint32_t* r) {
    asm volatile("ldmatrix.sync.aligned.m8n8.x4.shared.b16 {%0,%1,%2,%3}, [%4];"
                 : "=r"(r[0]), "=r"(r[1]), "=r"(r[2]), "=r"(r[3]) : "r"(addr));
}
__device__ __forceinline__ void ldsm2(uint32_t addr, uint32_t* r) {
    asm volatile("ldmatrix.sync.aligned.m8n8.x2.shared.b16 {%0,%1}, [%2];"
                 : "=r"(r[0]), "=r"(r[1]) : "r"(addr));
}
__device__ __forceinline__ void mma16816(float* c, const uint32_t* a, const uint32_t* b) {
    asm volatile(
        "mma.sync.aligned.m16n8k16.row.col.f32.bf16.bf16.f32 "
        "{%0,%1,%2,%3}, {%4,%5,%6,%7}, {%8,%9}, {%0,%1,%2,%3};"
        : "+f"(c[0]), "+f"(c[1]), "+f"(c[2]), "+f"(c[3])
        : "r"(a[0]), "r"(a[1]), "r"(a[2]), "r"(a[3]), "r"(b[0]), "r"(b[1]));
}
__device__ __forceinline__ void mma1688(float* c, const uint32_t* a, const uint32_t* b) {
    asm volatile(
        "mma.sync.aligned.m16n8k8.row.col.f32.tf32.tf32.f32 "
        "{%0,%1,%2,%3}, {%4,%5,%6,%7}, {%8,%9}, {%0,%1,%2,%3};"
        : "+f"(c[0]), "+f"(c[1]), "+f"(c[2]), "+f"(c[3])
        : "r"(a[0]), "r"(a[1]), "r"(a[2]), "r"(a[3]), "r"(b[0]), "r"(b[1]));
}
__device__ __forceinline__ uint32_t f2tf(float x) {
    uint32_t r; asm("cvt.rna.tf32.f32 %0, %1;" : "=r"(r) : "f"(x)); return r;
}
__device__ __forceinline__ float ex2f(float x) {
    float r; asm("ex2.approx.f32 %0, %1;" : "=f"(r) : "f"(x)); return r;
}

// ===================== scratch (device globals) =============================
#define QR ((size_t)16 * SEQ * DEPTH)      // one attn region (frag-major)
__device__ float g_bqkv[3 * DIM];
__device__ float g_b1f[HID];
__device__ __align__(16) __nv_bfloat16 g_qkvT_hi[3 * DIM * DIM], g_qkvT_lo[3 * DIM * DIM];
__device__ __align__(16) __nv_bfloat16 g_woT_hi[DIM * DIM],      g_woT_lo[DIM * DIM];
__device__ __align__(16) __nv_bfloat16 g_w1T_hi[HID * DIM],      g_w1T_lo[HID * DIM];
__device__ __align__(16) __nv_bfloat16 g_w2T_hi[DIM * HID],      g_w2T_lo[DIM * HID];
__device__ __align__(16) float g_attf[3 * 16 * SEQ * DEPTH];   // q,k,v frag-major
__device__ float g_ctx[MROWS * DIM];
__device__ float g_x1[MROWS * DIM];
__device__ float g_m1[MROWS * HID];

__device__ __forceinline__ void split_bf16(float x, __nv_bfloat16& h, __nv_bfloat16& l) {
    h = __float2bfloat16_rn(x);
    l = __float2bfloat16_rn(x - __bfloat162float(h));
}

// ===================== prep: elementwise split/transpose ====================
#define N_QKV (3 * DIM * DIM)          // 196608
#define N_W1  (DIM * HID)              // 262144
#define N_WO  (DIM * DIM)              // 65536
#define N_W2  (HID * DIM)              // 262144
#define N_TOT (N_QKV + N_W1 + N_WO + N_W2)

__global__ void prep_split(
    const float* __restrict__ g1, const float* __restrict__ v1,
    const float* __restrict__ g2, const float* __restrict__ v2,
    const float* __restrict__ wq, const float* __restrict__ wk,
    const float* __restrict__ wv, const float* __restrict__ w1,
    const float* __restrict__ wo, const float* __restrict__ w2)
{
    int i = blockIdx.x * 256 + threadIdx.x;
    if (i < N_QKV) {
        int d = i / (3 * DIM), col = i % (3 * DIM);
        const float* w = (col < DIM) ? wq : (col < 2 * DIM) ? wk : wv;
        int c = col & (DIM - 1);
        float a = g1[d] * rsqrtf(v1[d] + EPS);
        float val = a * w[d * DIM + c];
        __nv_bfloat16 h, l; split_bf16(val, h, l);
        g_qkvT_hi[col * DIM + d] = h; g_qkvT_lo[col * DIM + d] = l;
    } else if (i < N_QKV + N_W1) {
        int j = i - N_QKV; int d = j / HID, c = j % HID;
        float a = g2[d] * rsqrtf(v2[d] + EPS);
        float val = a * w1[j];
        __nv_bfloat16 h, l; split_bf16(val, h, l);
        g_w1T_hi[c * DIM + d] = h; g_w1T_lo[c * DIM + d] = l;
    } else if (i < N_QKV + N_W1 + N_WO) {
        int j = i - N_QKV - N_W1; int d = j / DIM, c = j % DIM;
        __nv_bfloat16 h, l; split_bf16(wo[j], h, l);
        g_woT_hi[c * DIM + d] = h; g_woT_lo[c * DIM + d] = l;
    } else if (i < N_TOT) {
        int j = i - N_QKV - N_W1 - N_WO; int k = j / DIM, n = j % DIM;
        __nv_bfloat16 h, l; split_bf16(w2[j], h, l);
        g_w2T_hi[n * HID + k] = h; g_w2T_lo[n * HID + k] = l;
    }
}

__global__ void prep_bias(
    const float* __restrict__ g1, const float* __restrict__ b1,
    const float* __restrict__ m1, const float* __restrict__ v1,
    const float* __restrict__ g2, const float* __restrict__ b2,
    const float* __restrict__ m2, const float* __restrict__ v2,
    const float* __restrict__ wq, const float* __restrict__ wk,
    const float* __restrict__ wv,
    const float* __restrict__ bq, const float* __restrict__ bk,
    const float* __restrict__ bv, const float* __restrict__ w1)
{
    int blk = blockIdx.x, t = threadIdx.x;
    if (blk < 3) {
        const float* w  = blk == 0 ? wq : blk == 1 ? wk : wv;
        const float* bb = blk == 0 ? bq : blk == 1 ? bk : bv;
        float acc = bb[t];
        for (int d = 0; d < DIM; d++) {
            float a = g1[d] * rsqrtf(v1[d] + EPS);
            float c = b1[d] - m1[d] * a;
            acc += c * w[d * DIM + t];
        }
        g_bqkv[blk * DIM + t] = acc;
    } else {
        int cb = (blk - 3) * 256;
        float acc = 0.f;
        for (int d = 0; d < DIM; d++) {
            float a = g2[d] * rsqrtf(v2[d] + EPS);
            float c = b2[d] - m2[d] * a;
            acc += c * w1[d * HID + cb + t];
        }
        g_b1f[cb + t] = acc;
    }
}

// ===================== mma.sync split-bf16 GEMM =============================
// mode 0: C = A@B + bias (+resid). mode 1: + GELU. mode 2: frag-major q/k/v
// (tf32-rounded, q pre-scaled by 0.125*log2e) into g_attf.
#define ASTRIDE 40
#define TILE_B  (128 * ASTRIDE * 2)
#define BUF_B   (4 * TILE_B)
#define GSMEM_B (2 * BUF_B)

__global__ void __launch_bounds__(256)
gemm_mma(const float* __restrict__ A,
         const __nv_bfloat16* __restrict__ Bth, const __nv_bfloat16* __restrict__ Btl,
         const float* __restrict__ bias, const float* __restrict__ resid,
         float* __restrict__ C, float* __restrict__ attf,
         int M, int N, int K, int mode)
{
    extern __shared__ __align__(16) char smem[];
    const int tid  = threadIdx.x;
    const int wid  = tid >> 5;
    const int lane = tid & 31;
    const int m0 = blockIdx.y * 128;
    const int n0 = blockIdx.x * 128;
    const int warpM = (wid & 1) * 64;
    const int warpN = (wid >> 1) * 32;

    const int lrow = tid >> 1;
    const int lko  = (tid & 1) * 16;

    const int aRowOff = (lane & 7) + ((lane >> 3) & 1) * 8;
    const int aKpart  = ((lane >> 4) & 1) * 8;
    const int bl2     = lane & 15;
    const int bRowOff = bl2 & 7;
    const int bKpart  = (bl2 >> 3) * 8;

    const uint32_t sbase = smem_u32(smem);

    float acc[4][4][4];
#pragma unroll
    for (int i = 0; i < 4; i++)
#pragma unroll
        for (int j = 0; j < 4; j++)
#pragma unroll
            for (int e = 0; e < 4; e++) acc[i][j][e] = 0.f;

    const int nch = K >> 5;
    float4 aR[4];
    uint4  bhR[2], blR[2];

    {
        const float* ap = A + (size_t)(m0 + lrow) * K + lko;
#pragma unroll
        for (int i = 0; i < 4; i++) aR[i] = ((const float4*)ap)[i];
        const __nv_bfloat16* bp = Bth + (size_t)(n0 + lrow) * K + lko;
        const __nv_bfloat16* lp = Btl + (size_t)(n0 + lrow) * K + lko;
        bhR[0] = ((const uint4*)bp)[0]; bhR[1] = ((const uint4*)bp)[1];
        blR[0] = ((const uint4*)lp)[0]; blR[1] = ((const uint4*)lp)[1];
    }

    for (int c = 0; c < nch; c++) {
        const int buf = c & 1;
        char* base = smem + buf * BUF_B;
        __syncthreads();
        {
            const int rb = lrow * (ASTRIDE * 2) + lko * 2;
#pragma unroll
            for (int i = 0; i < 2; i++) {
                float4 f0 = aR[i * 2], f1 = aR[i * 2 + 1];
                __nv_bfloat162 h01 = __floats2bfloat162_rn(f0.x, f0.y);
                __nv_bfloat162 h23 = __floats2bfloat162_rn(f0.z, f0.w);
                __nv_bfloat162 h45 = __floats2bfloat162_rn(f1.x, f1.y);
                __nv_bfloat162 h67 = __floats2bfloat162_rn(f1.z, f1.w);
                __nv_bfloat162 l01 = __floats2bfloat162_rn(f0.x - __bfloat162float(h01.x),
                                                           f0.y - __bfloat162float(h01.y));
                __nv_bfloat162 l23 = __floats2bfloat162_rn(f0.z - __bfloat162float(h23.x),
                                                           f0.w - __bfloat162float(h23.y));
                __nv_bfloat162 l45 = __floats2bfloat162_rn(f1.x - __bfloat162float(h45.x),
                                                           f1.y - __bfloat162float(h45.y));
                __nv_bfloat162 l67 = __floats2bfloat162_rn(f1.z - __bfloat162float(h67.x),
                                                           f1.w - __bfloat162float(h67.y));
                uint4 hv = { *(uint32_t*)&h01, *(uint32_t*)&h23,
                             *(uint32_t*)&h45, *(uint32_t*)&h67 };
                uint4 lv = { *(uint32_t*)&l01, *(uint32_t*)&l23,
                             *(uint32_t*)&l45, *(uint32_t*)&l67 };
                *(uint4*)(base + rb + i * 16)          = hv;
                *(uint4*)(base + TILE_B + rb + i * 16) = lv;
            }
            *(uint4*)(base + 2 * TILE_B + rb)      = bhR[0];
            *(uint4*)(base + 2 * TILE_B + rb + 16) = bhR[1];
            *(uint4*)(base + 3 * TILE_B + rb)      = blR[0];
            *(uint4*)(base + 3 * TILE_B + rb + 16) = blR[1];
        }
        __syncthreads();

        if (c + 1 < nch) {
            const int k0 = (c + 1) << 5;
            const float* ap = A + (size_t)(m0 + lrow) * K + k0 + lko;
#pragma unroll
            for (int i = 0; i < 4; i++) aR[i] = ((const float4*)ap)[i];
            const __nv_bfloat16* bp = Bth + (size_t)(n0 + lrow) * K + k0 + lko;
            const __nv_bfloat16* lp = Btl + (size_t)(n0 + lrow) * K + k0 + lko;
            bhR[0] = ((const uint4*)bp)[0]; bhR[1] = ((const uint4*)bp)[1];
            blR[0] = ((const uint4*)lp)[0]; blR[1] = ((const uint4*)lp)[1];
        }

        const uint32_t Ah = sbase + buf * BUF_B;
        const uint32_t Al = Ah + TILE_B;
        const uint32_t Bh = Ah + 2 * TILE_B;
        const uint32_t Bl = Ah + 3 * TILE_B;
#pragma unroll
        for (int ks = 0; ks < 2; ks++) {
            uint32_t ah[4][4], al[4][4], bh[4][2], blf[4][2];
#pragma unroll
            for (int mi = 0; mi < 4; mi++) {
                uint32_t off = ((warpM + mi * 16 + aRowOff) * ASTRIDE
                                + ks * 16 + aKpart) * 2;
                ldsm4(Ah + off, ah[mi]);
                ldsm4(Al + off, al[mi]);
            }
#pragma unroll
            for (int nj = 0; nj < 4; nj++) {
                uint32_t off = ((warpN + nj * 8 + bRowOff) * ASTRIDE
                                + ks * 16 + bKpart) * 2;
                ldsm2(Bh + off, bh[nj]);
                ldsm2(Bl + off, blf[nj]);
            }
#pragma unroll
            for (int mi = 0; mi < 4; mi++)
#pragma unroll
                for (int nj = 0; nj < 4; nj++) {
                    mma16816(acc[mi][nj], ah[mi], bh[nj]);
                    mma16816(acc[mi][nj], ah[mi], blf[nj]);
                    mma16816(acc[mi][nj], al[mi], bh[nj]);
                }
        }
    }

    // ---- epilogue ----
    const int g   = lane >> 2;
    const int tig = lane & 3;
#pragma unroll
    for (int mi = 0; mi < 4; mi++) {
#pragma unroll
        for (int half = 0; half < 2; half++) {
            int row = m0 + warpM + mi * 16 + g + half * 8;
#pragma unroll
            for (int nj = 0; nj < 4; nj++) {
                int col = n0 + warpN + nj * 8 + tig * 2;
                float vx = acc[mi][nj][half * 2 + 0];
                float vy = acc[mi][nj][half * 2 + 1];
                if (bias)  { vx += bias[col]; vy += bias[col + 1]; }
                if (mode == 2) {
                    // frag-major q/k/v output
                    int sect = col >> 8;
                    int hh   = (col >> 6) & 3;
                    int d    = col & 63;
                    int b    = row >> 11, sq = row & (SEQ - 1);
                    int bhx  = b * 4 + hh;
                    if (sect == 0) { vx *= QSC; vy *= QSC; }
                    vx = __uint_as_float(f2tf(vx));
                    vy = __uint_as_float(f2tf(vy));
                    size_t fx, fy;
                    if (sect == 0) {
                        int qt = sq >> 7, r = sq & 127;
                        int mtile = r >> 4, r8 = r & 7, hf = (r >> 3) & 1;
                        int kc = d >> 3, ch = (d >> 2) & 1;
                        size_t bse = ((size_t)bhx * 16 + qt) * 8192
                                   + (mtile * 8 + kc) * 128
                                   + (r8 * 4 + (d & 3)) * 4 + hf + 2 * ch;
                        fx = bse; fy = bse + 4;
                    } else if (sect == 1) {
                        int kt = sq >> 6, key = sq & 63;
                        int nt = key >> 3, kcp = d >> 4;
                        int krr = ((d >> 3) & 1) * 2 + ((d >> 2) & 1);
                        size_t bse = ((size_t)bhx * 32 + kt) * 4096
                                   + (nt * 4 + kcp) * 128
                                   + ((key & 7) * 4 + (d & 3)) * 4 + krr;
                        fx = bse; fy = bse + 4;
                    } else {
                        int kt = sq >> 6, key = sq & 63;
                        int nt = d >> 3, kcp = key >> 4;
                        int rr = ((key >> 3) & 1) * 2 + ((key >> 2) & 1);
                        size_t bse = ((size_t)bhx * 32 + kt) * 4096
                                   + (nt * 4 + kcp) * 128
                                   + ((d & 7) * 4 + (key & 3)) * 4 + rr;
                        fx = bse; fy = bse + 16;
                    }
                    float* reg = attf + (size_t)sect * QR;
                    reg[fx] = vx; reg[fy] = vy;
                } else {
                    if (resid) {
                        const float* rp = resid + (size_t)row * N + col;
                        vx += rp[0]; vy += rp[1];
                    }
                    if (mode == 1) {
                        vx = 0.5f * vx * (1.0f + erff(vx * 0.70710678118654752f));
                        vy = 0.5f * vy * (1.0f + erff(vy * 0.70710678118654752f));
                    }
                    *(float2*)(C + (size_t)row * N + col) = make_float2(vx, vy);
                }
            }
        }
    }
}

// ===================== flash attention, tf32 mma ============================
// CTA: 128 queries of one (b,h), 4 warps x 32 rows. Key tiles of 64.
// Q/K/V arrive in gmem frag-major; tile loads are straight uint4 copies.
#define ATP 132                          // padded tile stride (floats)
#define ATT_SMEM (128 * ATP * 4)         // 67584 bytes

__global__ void __launch_bounds__(128)
attn_tf32(const float* __restrict__ attf, float* __restrict__ ctx)
{
    extern __shared__ __align__(16) float sm[];
    float* Qs = sm;                  // 64 tiles
    float* Ks = sm + 64 * ATP;       // 32 tiles
    float* Vs = sm + 96 * ATP;       // 32 tiles

    const int tid  = threadIdx.x;
    const int wid  = tid >> 5;
    const int lane = tid & 31;
    const int bh   = blockIdx.y;
    const int q0   = blockIdx.x * 128;

    // ---- Q tile copy (once) ----
    {
        const uint4* qsrc = (const uint4*)(attf
            + ((size_t)bh * 16 + blockIdx.x) * 8192);
#pragma unroll
        for (int u = 0; u < 16; u++) {
            int g4 = tid + u * 128;
            *(uint4*)(Qs + (g4 >> 5) * ATP + (g4 & 31) * 4) = qsrc[g4];
        }
    }

    float o[2][8][4];
#pragma unroll
    for (int mt = 0; mt < 2; mt++)
#pragma unroll
        for (int nt = 0; nt < 8; nt++)
#pragma unroll
            for (int e = 0; e < 4; e++) o[mt][nt][e] = 0.f;
    float mrow[4] = { -1e30f, -1e30f, -1e30f, -1e30f };
    float lsum[4] = { 0.f, 0.f, 0.f, 0.f };

    const int srcA = (lane & 28) | ((lane & 3) >> 1);
    const int srcB = srcA + 2;
    const bool oddl = lane & 1;

    const uint4* kbase = (const uint4*)(attf + QR)     + (size_t)bh * 32 * 1024;
    const uint4* vbase = (const uint4*)(attf + 2 * QR) + (size_t)bh * 32 * 1024;

    for (int kt = 0; kt < SEQ / 64; kt++) {
        __syncthreads();
        {
            const uint4* ks = kbase + (size_t)kt * 1024;
            const uint4* vs = vbase + (size_t)kt * 1024;
#pragma unroll
            for (int u = 0; u < 8; u++) {
                int g4 = tid + u * 128;
                int off = (g4 >> 5) * ATP + (g4 & 31) * 4;
                *(uint4*)(Ks + off) = ks[g4];
                *(uint4*)(Vs + off) = vs[g4];
            }
        }
        __syncthreads();

        // ---- scores S[32 x 64] per warp ----
        float s[2][8][4];
#pragma unroll
        for (int mt = 0; mt < 2; mt++)
#pragma unroll
            for (int nt = 0; nt < 8; nt++)
#pragma unroll
                for (int e = 0; e < 4; e++) s[mt][nt][e] = 0.f;

#pragma unroll
        for (int kcp = 0; kcp < 4; kcp++) {
            uint4 aE0 = *(const uint4*)(Qs + ((wid * 2 + 0) * 8 + 2 * kcp) * ATP + lane * 4);
            uint4 aO0 = *(const uint4*)(Qs + ((wid * 2 + 0) * 8 + 2 * kcp + 1) * ATP + lane * 4);
            uint4 aE1 = *(const uint4*)(Qs + ((wid * 2 + 1) * 8 + 2 * kcp) * ATP + lane * 4);
            uint4 aO1 = *(const uint4*)(Qs + ((wid * 2 + 1) * 8 + 2 * kcp + 1) * ATP + lane * 4);
#pragma unroll
            for (int nt = 0; nt < 8; nt++) {
                uint4 kb = *(const uint4*)(Ks + (nt * 4 + kcp) * ATP + lane * 4);
                uint32_t bE[2] = { kb.x, kb.y }, bO[2] = { kb.z, kb.w };
                mma1688(s[0][nt], (const uint32_t*)&aE0, bE);
                mma1688(s[0][nt], (const uint32_t*)&aO0, bO);
                mma1688(s[1][nt], (const uint32_t*)&aE1, bE);
                mma1688(s[1][nt], (const uint32_t*)&aO1, bO);
            }
        }

        // ---- online softmax (log2 domain) ----
        float mx[4] = { -1e30f, -1e30f, -1e30f, -1e30f };
#pragma unroll
        for (int mt = 0; mt < 2; mt++)
#pragma unroll
            for (int nt = 0; nt < 8; nt++) {
                mx[2 * mt + 0] = fmaxf(mx[2 * mt + 0], fmaxf(s[mt][nt][0], s[mt][nt][1]));
                mx[2 * mt + 1] = fmaxf(mx[2 * mt + 1], fmaxf(s[mt][nt][2], s[mt][nt][3]));
            }
        float sc[4], ls[4] = { 0.f, 0.f, 0.f, 0.f };
#pragma unroll
        for (int i = 0; i < 4; i++) {
            mx[i] = fmaxf(mx[i], __shfl_xor_sync(0xffffffff, mx[i], 1));
            mx[i] = fmaxf(mx[i], __shfl_xor_sync(0xffffffff, mx[i], 2));
            float mn = fmaxf(mrow[i], mx[i]);
            sc[i] = ex2f(mrow[i] - mn);
            mrow[i] = mn;
        }
#pragma unroll
        for (int mt = 0; mt < 2; mt++)
#pragma unroll
            for (int nt = 0; nt < 8; nt++) {
                s[mt][nt][0] = ex2f(s[mt][nt][0] - mrow[2 * mt]);
                s[mt][nt][1] = ex2f(s[mt][nt][1] - mrow[2 * mt]);
                s[mt][nt][2] = ex2f(s[mt][nt][2] - mrow[2 * mt + 1]);
                s[mt][nt][3] = ex2f(s[mt][nt][3] - mrow[2 * mt + 1]);
                ls[2 * mt]     += s[mt][nt][0] + s[mt][nt][1];
                ls[2 * mt + 1] += s[mt][nt][2] + s[mt][nt][3];
            }
#pragma unroll
        for (int i = 0; i < 4; i++) {
            ls[i] += __shfl_xor_sync(0xffffffff, ls[i], 1);
            ls[i] += __shfl_xor_sync(0xffffffff, ls[i], 2);
            lsum[i] = lsum[i] * sc[i] + ls[i];
        }
#pragma unroll
        for (int mt = 0; mt < 2; mt++)
#pragma unroll
            for (int nt = 0; nt < 8; nt++) {
                o[mt][nt][0] *= sc[2 * mt];     o[mt][nt][1] *= sc[2 * mt];
                o[mt][nt][2] *= sc[2 * mt + 1]; o[mt][nt][3] *= sc[2 * mt + 1];
            }

        // ---- PV: o += P @ V ----
#pragma unroll
        for (int kcp = 0; kcp < 4; kcp++) {
            uint32_t pa[2][2][4];
#pragma unroll
            for (int kk = 0; kk < 2; kk++) {
                int kc = 2 * kcp + kk;
#pragma unroll
                for (int mt = 0; mt < 2; mt++) {
                    float v00 = __shfl_sync(0xffffffff, s[mt][kc][0], srcA);
                    float v01 = __shfl_sync(0xffffffff, s[mt][kc][1], srcA);
                    float v10 = __shfl_sync(0xffffffff, s[mt][kc][2], srcA);
                    float v11 = __shfl_sync(0xffffffff, s[mt][kc][3], srcA);
                    float v20 = __shfl_sync(0xffffffff, s[mt][kc][0], srcB);
                    float v21 = __shfl_sync(0xffffffff, s[mt][kc][1], srcB);
                    float v30 = __shfl_sync(0xffffffff, s[mt][kc][2], srcB);
                    float v31 = __shfl_sync(0xffffffff, s[mt][kc][3], srcB);
                    pa[kk][mt][0] = f2tf(oddl ? v01 : v00);
                    pa[kk][mt][1] = f2tf(oddl ? v11 : v10);
                    pa[kk][mt][2] = f2tf(oddl ? v21 : v20);
                    pa[kk][mt][3] = f2tf(oddl ? v31 : v30);
                }
            }
#pragma unroll
            for (int nt = 0; nt < 8; nt++) {
                uint4 vb = *(const uint4*)(Vs + (nt * 4 + kcp) * ATP + lane * 4);
                uint32_t bE[2] = { vb.x, vb.y }, bO[2] = { vb.z, vb.w };
                mma1688(o[0][nt], pa[0][0], bE);
                mma1688(o[0][nt], pa[1][0], bO);
                mma1688(o[1][nt], pa[0][1], bE);
                mma1688(o[1][nt], pa[1][1], bO);
            }
        }
    }

    // ---- write ctx ----
    float inv[4];
#pragma unroll
    for (int i = 0; i < 4; i++) inv[i] = 1.f / lsum[i];
    const int b  = bh >> 2;
    const int hh = bh & 3;
    const int g  = lane >> 2;
    const int tg = (lane & 3) * 2;
#pragma unroll
    for (int mt = 0; mt < 2; mt++) {
        int ra = q0 + wid * 32 + mt * 16 + g;
#pragma unroll
        for (int nt = 0; nt < 8; nt++) {
            int col = hh * DEPTH + tg + nt * 8;
            *(float2*)(ctx + (size_t)(b * SEQ + ra) * DIM + col) =
                make_float2(o[mt][nt][0] * inv[2 * mt], o[mt][nt][1] * inv[2 * mt]);
            *(float2*)(ctx + (size_t)(b * SEQ + ra + 8) * DIM + col) =
                make_float2(o[mt][nt][2] * inv[2 * mt + 1], o[mt][nt][3] * inv[2 * mt + 1]);
        }
    }
}

// ===================== launch ===============================================
extern "C" void kernel_launch(void* const* d_in, const int* in_sizes, int n_in,
                              void* d_out, int out_size)
{
    const float* x    = (const float*)d_in[0];
    const float* b1g  = (const float*)d_in[1];
    const float* b1b  = (const float*)d_in[2];
    const float* b1m  = (const float*)d_in[3];
    const float* b1v  = (const float*)d_in[4];
    const float* wq   = (const float*)d_in[5];
    const float* bq   = (const float*)d_in[6];
    const float* wk   = (const float*)d_in[7];
    const float* bk   = (const float*)d_in[8];
    const float* wv   = (const float*)d_in[9];
    const float* bv   = (const float*)d_in[10];
    const float* wo   = (const float*)d_in[11];
    const float* bo   = (const float*)d_in[12];
    const float* b2g  = (const float*)d_in[13];
    const float* b2b  = (const float*)d_in[14];
    const float* b2m  = (const float*)d_in[15];
    const float* b2v  = (const float*)d_in[16];
    const float* w1   = (const float*)d_in[17];
    const float* w2   = (const float*)d_in[18];
    float* out = (float*)d_out;

    float *p_bqkv, *p_b1f, *p_ctx, *p_x1, *p_m1, *p_attf;
    __nv_bfloat16 *p_qkvTh, *p_qkvTl, *p_woTh, *p_woTl, *p_w1Th, *p_w1Tl, *p_w2Th, *p_w2Tl;
    cudaGetSymbolAddress((void**)&p_bqkv,  g_bqkv);
    cudaGetSymbolAddress((void**)&p_b1f,   g_b1f);
    cudaGetSymbolAddress((void**)&p_ctx,   g_ctx);
    cudaGetSymbolAddress((void**)&p_x1,    g_x1);
    cudaGetSymbolAddress((void**)&p_m1,    g_m1);
    cudaGetSymbolAddress((void**)&p_attf,  g_attf);
    cudaGetSymbolAddress((void**)&p_qkvTh, g_qkvT_hi);
    cudaGetSymbolAddress((void**)&p_qkvTl, g_qkvT_lo);
    cudaGetSymbolAddress((void**)&p_woTh,  g_woT_hi);
    cudaGetSymbolAddress((void**)&p_woTl,  g_woT_lo);
    cudaGetSymbolAddress((void**)&p_w1Th,  g_w1T_hi);
    cudaGetSymbolAddress((void**)&p_w1Tl,  g_w1T_lo);
    cudaGetSymbolAddress((void**)&p_w2Th,  g_w2T_hi);
    cudaGetSymbolAddress((void**)&p_w2Tl,  g_w2T_lo);

    cudaFuncSetAttribute(gemm_mma, cudaFuncAttributeMaxDynamicSharedMemorySize, GSMEM_B);
    cudaFuncSetAttribute(attn_tf32, cudaFuncAttributeMaxDynamicSharedMemorySize, ATT_SMEM);

    // 1. prep: weight split/transpose (elementwise) + bias folds
    prep_split<<<(N_TOT + 255) / 256, 256>>>(b1g, b1v, b2g, b2v,
                                             wq, wk, wv, w1, wo, w2);
    prep_bias<<<7, 256>>>(b1g, b1b, b1m, b1v, b2g, b2b, b2m, b2v,
                          wq, wk, wv, bq, bk, bv, w1);

    // 2. QKV projection, frag-major tf32 output into g_attf
    gemm_mma<<<dim3(6, 64), 256, GSMEM_B>>>(
        x, p_qkvTh, p_qkvTl, p_bqkv, nullptr, p_ctx, p_attf,
        MROWS, 3 * DIM, DIM, 2);

    // 3. flash attention (tf32 tensor cores) -> g_ctx
    attn_tf32<<<dim3(SEQ / 128, BATCH * HEADS), 128, ATT_SMEM>>>(p_attf, p_ctx);

    // 4. out projection + residual: g_x1 = ctx @ wo + bo + x
    gemm_mma<<<dim3(2, 64), 256, GSMEM_B>>>(
        p_ctx, p_woTh, p_woTl, bo, x, p_x1, p_attf, MROWS, DIM, DIM, 0);

    // 5. FFN1 (BN2 folded) + GELU
    gemm_mma<<<dim3(8, 64), 256, GSMEM_B>>>(
        p_x1, p_w1Th, p_w1Tl, p_b1f, nullptr, p_m1, p_attf, MROWS, HID, DIM, 1);

    // 6. FFN2 + residual: out = m1 @ w2 + x1
    gemm_mma<<<dim3(2, 64), 256, GSMEM_B>>>(
        p_m1, p_w2Th, p_w2Tl, nullptr, p_x1, out, p_attf, MROWS, DIM, HID, 0);
}